// round 9
// baseline (speedup 1.0000x reference)
#include <cuda_runtime.h>
#include <cuda_bf16.h>

namespace {
constexpr int Hc = 16;
constexpr int Sc = 2048;
constexpr int Dc = 128;
constexpr int BM = 64;
constexpr int BN = 64;
constexpr int NT = 256;

// dynamic smem layout (in floats)
constexpr int OFF_QT   = 0;      // Q^T swizzled  [d][ii]  128x64
constexpr int OFF_KV   = 8192;   // K^T swizzled (phase1) / V row-major (phase2)
constexpr int OFF_ST   = 16384;  // S^T swizzled  [jj][ii] 64x64
constexpr int OFF_ROWP = 20480;  // gamma^ii
constexpr int OFF_COLP = 20544;  // gamma^-jj
constexpr int OFF_INVL = 20608;  // 1/L for this block's 64 query rows
constexpr int SMEM_FLOATS = 20672;
constexpr int SMEM_BYTES  = SMEM_FLOATS * 4;   // 82688 B -> 2 CTAs/SM
}

__global__ __launch_bounds__(NT, 2)
void retention_fp32_kernel(const float* __restrict__ Qg,
                           const float* __restrict__ Kg,
                           const float* __restrict__ Vg,
                           float* __restrict__ Og)
{
    extern __shared__ float sm[];
    float* QT   = sm + OFF_QT;
    float* KV   = sm + OFF_KV;
    float* St   = sm + OFF_ST;
    float* rowp = sm + OFF_ROWP;
    float* colp = sm + OFF_COLP;
    float* invL = sm + OFF_INVL;

    const int tid = threadIdx.x;
    const int tx  = tid & 15;
    const int ty  = tid >> 4;
    const int a0  = ty * 4;          // query-row group within tile
    const int b0  = tx * 4;          // key-col group within tile

    const int qt  = (int)(gridDim.x - 1u - blockIdx.x);  // heavy tiles first
    const int h   = blockIdx.y;
    const int bb  = blockIdx.z;
    const int qi0 = qt * BM;

    const double g   = 1.0 - exp2(-(5.0 + (double)h));
    const double lg  = log2(g);
    const float  lgf = (float)lg;

    const size_t base = ((size_t)bb * Hc + h) * (size_t)Sc * Dc;
    const float* Qp = Qg + base;
    const float* Kp = Kg + base;
    const float* Vp = Vg + base;
    float*       Op = Og + base;

    // per-block tables
    if (tid < BM) {
        rowp[tid] = (float)exp2(lg * (double)tid);
        colp[tid] = (float)exp2(-lg * (double)tid);
        double gi1 = exp2(lg * (double)(qi0 + tid + 1));
        invL[tid] = (float)((1.0 - g) / (1.0 - gi1));   // 1/L, L=(1-g^{i+1})/(1-g)
    }
    __syncthreads();
    const float cp63 = colp[63];

    // Load Q^T (scaled by 1/L) into swizzled transposed smem.
    // element (d,row) stored at  d*64 + (row ^ ((d>>2 & 15)*4))
    #pragma unroll
    for (int it = 0; it < 8; ++it) {
        int idx = tid + it * NT;     // 0..2047
        int row = idx >> 5;
        int d4  = idx & 31;
        float4 v = *(const float4*)(Qp + (size_t)(qi0 + row) * Dc + d4 * 4);
        float scl = invL[row];
        int col = row ^ ((d4 & 15) * 4);
        float* dst = QT + d4 * 256 + col;   // d4*256 == (4*d4)*64
        dst[0]   = v.x * scl;
        dst[64]  = v.y * scl;
        dst[128] = v.z * scl;
        dst[192] = v.w * scl;
    }

    float o[4][8];                     // rows a0+r ; cols b0+c and 64+b0+c
    #pragma unroll
    for (int r = 0; r < 4; ++r)
        #pragma unroll
        for (int c = 0; c < 8; ++c) o[r][c] = 0.f;
    float rsum[4] = {0.f, 0.f, 0.f, 0.f};

    for (int kt = 0; kt <= qt; ++kt) {
        const int kj0 = kt * BN;
        const float tf = exp2f(lgf * (float)(qi0 - kj0));  // gamma^(qi0-kj0)
        if (tf * cp63 < 1e-12f) continue;   // uniform skip: tile contributes ~0

        __syncthreads();   // previous phase-2 done reading KV / St

        // ---- load K^T (transposed, swizzled) ----
        #pragma unroll
        for (int it = 0; it < 8; ++it) {
            int idx = tid + it * NT;
            int row = idx >> 5;
            int d4  = idx & 31;
            float4 v = *(const float4*)(Kp + (size_t)(kj0 + row) * Dc + d4 * 4);
            int col = row ^ ((d4 & 15) * 4);
            float* dst = KV + d4 * 256 + col;
            dst[0] = v.x; dst[64] = v.y; dst[128] = v.z; dst[192] = v.w;
        }
        __syncthreads();

        // ---- phase 1: S = (Q/L) . K^T  (inner dim d) ----
        float s[4][4];
        #pragma unroll
        for (int r = 0; r < 4; ++r)
            #pragma unroll
            for (int c = 0; c < 4; ++c) s[r][c] = 0.f;

        #pragma unroll 4
        for (int d = 0; d < 128; ++d) {
            const int sw = ((d >> 2) & 15) * 4;
            const float4 a  = *(const float4*)(QT + d * 64 + (a0 ^ sw));
            const float4 k4 = *(const float4*)(KV + d * 64 + (b0 ^ sw));
            s[0][0] += a.x * k4.x; s[0][1] += a.x * k4.y; s[0][2] += a.x * k4.z; s[0][3] += a.x * k4.w;
            s[1][0] += a.y * k4.x; s[1][1] += a.y * k4.y; s[1][2] += a.y * k4.z; s[1][3] += a.y * k4.w;
            s[2][0] += a.z * k4.x; s[2][1] += a.z * k4.y; s[2][2] += a.z * k4.z; s[2][3] += a.z * k4.w;
            s[3][0] += a.w * k4.x; s[3][1] += a.w * k4.y; s[3][2] += a.w * k4.z; s[3][3] += a.w * k4.w;
        }

        // ---- decay + causal mask + rowsum partials ----
        const bool diag = (kj0 == qi0);
        #pragma unroll
        for (int r = 0; r < 4; ++r) {
            const float rp = rowp[a0 + r] * tf;
            #pragma unroll
            for (int c = 0; c < 4; ++c) {
                float f = rp * colp[b0 + c];
                if (diag && (b0 + c > a0 + r)) f = 0.f;
                s[r][c] *= f;
            }
            rsum[r] += (s[r][0] + s[r][1]) + (s[r][2] + s[r][3]);
        }

        // ---- write S^T to smem, swizzled: (j,i) at j*64 + (i ^ ((j>>2 & 7)*4)) ----
        {
            const int swj = (tx & 7) * 4;   // (j>>2)&7 == tx&7 for j=b0+c
            #pragma unroll
            for (int c = 0; c < 4; ++c) {
                *(float4*)(St + (b0 + c) * 64 + (a0 ^ swj)) =
                    make_float4(s[0][c], s[1][c], s[2][c], s[3][c]);
            }
        }
        __syncthreads();   // St ready; all threads done reading KV-as-K

        // ---- load V (row-major) into KV ----
        #pragma unroll
        for (int it = 0; it < 8; ++it) {
            int idx = tid + it * NT;
            int row = idx >> 5;
            int c4  = idx & 31;
            *(float4*)(KV + row * 128 + c4 * 4) =
                *(const float4*)(Vp + (size_t)(kj0 + row) * Dc + c4 * 4);
        }
        __syncthreads();

        // ---- phase 2: O += S . V  (inner dim j) ----
        #pragma unroll 4
        for (int j = 0; j < 64; ++j) {
            const int swj = ((j >> 2) & 7) * 4;
            const float4 a  = *(const float4*)(St + j * 64 + (a0 ^ swj));
            const float4 v0 = *(const float4*)(KV + j * 128 + b0);
            const float4 v1 = *(const float4*)(KV + j * 128 + 64 + b0);
            o[0][0] += a.x * v0.x; o[0][1] += a.x * v0.y; o[0][2] += a.x * v0.z; o[0][3] += a.x * v0.w;
            o[0][4] += a.x * v1.x; o[0][5] += a.x * v1.y; o[0][6] += a.x * v1.z; o[0][7] += a.x * v1.w;
            o[1][0] += a.y * v0.x; o[1][1] += a.y * v0.y; o[1][2] += a.y * v0.z; o[1][3] += a.y * v0.w;
            o[1][4] += a.y * v1.x; o[1][5] += a.y * v1.y; o[1][6] += a.y * v1.z; o[1][7] += a.y * v1.w;
            o[2][0] += a.z * v0.x; o[2][1] += a.z * v0.y; o[2][2] += a.z * v0.z; o[2][3] += a.z * v0.w;
            o[2][4] += a.z * v1.x; o[2][5] += a.z * v1.y; o[2][6] += a.z * v1.z; o[2][7] += a.z * v1.w;
            o[3][0] += a.w * v0.x; o[3][1] += a.w * v0.y; o[3][2] += a.w * v0.z; o[3][3] += a.w * v0.w;
            o[3][4] += a.w * v1.x; o[3][5] += a.w * v1.y; o[3][6] += a.w * v1.z; o[3][7] += a.w * v1.w;
        }
    }

    // ---- reduce rowsums across the 16 column-threads (XOR<=8 stays within
    //      the 16-lane half-warp that shares ty, i.e. shares rows) ----
    #pragma unroll
    for (int off = 8; off > 0; off >>= 1) {
        #pragma unroll
        for (int r = 0; r < 4; ++r)
            rsum[r] += __shfl_xor_sync(0xffffffffu, rsum[r], off);
    }

    // ---- epilogue: P = max(|rowsum|, 1); O /= P; store ----
    #pragma unroll
    for (int r = 0; r < 4; ++r) {
        float p  = fmaxf(fabsf(rsum[r]), 1.0f);
        float ip = 1.0f / p;
        float* orow = Op + (size_t)(qi0 + a0 + r) * Dc;
        float4 w0 = make_float4(o[r][0] * ip, o[r][1] * ip, o[r][2] * ip, o[r][3] * ip);
        float4 w1 = make_float4(o[r][4] * ip, o[r][5] * ip, o[r][6] * ip, o[r][7] * ip);
        *(float4*)(orow + b0)      = w0;
        *(float4*)(orow + 64 + b0) = w1;
    }
}

extern "C" void kernel_launch(void* const* d_in, const int* in_sizes, int n_in,
                              void* d_out, int out_size)
{
    (void)n_in; (void)out_size;
    const float* q = (const float*)d_in[0];
    const float* k = (const float*)d_in[1];
    const float* v = (const float*)d_in[2];
    // d_in[3] (omask) intentionally unused: mask and L are computed analytically.
    float* o = (float*)d_out;

    const int Bdim = in_sizes[0] / (Hc * Sc * Dc);   // = 2

    cudaFuncSetAttribute(retention_fp32_kernel,
                         cudaFuncAttributeMaxDynamicSharedMemorySize, SMEM_BYTES);

    dim3 grid(Sc / BM, Hc, Bdim);
    retention_fp32_kernel<<<grid, NT, SMEM_BYTES>>>(q, k, v, o);
}